// round 8
// baseline (speedup 1.0000x reference)
#include <cuda_runtime.h>
#include <math.h>

#define MAXB 4096
__device__ float    g_seg_bce[MAXB];   // zero-init at module load; last block re-zeroes
__device__ float    g_seg_cnt[MAXB];
__device__ unsigned g_ticket;          // zero-init; last block resets

__device__ __forceinline__ float bce_fast(float p, float t) {
    float lp = fmaxf(__logf(p),        -100.0f);   // __logf(0) = -inf -> -100
    float lq = fmaxf(__logf(1.0f - p), -100.0f);
    return -(t * lp + (1.0f - t) * lq);
}

// release-ordered ticket increment: orders this block's prior REDs (L2)
// before the increment WITHOUT a gpu-scope fence (no CCTL.IVALL / L1 flush).
__device__ __forceinline__ unsigned ticket_add_release(unsigned* addr) {
    unsigned old;
    asm volatile("atom.add.release.gpu.global.u32 %0, [%1], 1;"
                 : "=r"(old) : "l"(addr) : "memory");
    return old;
}

__global__ void __launch_bounds__(256) fused_kernel(
        const float* __restrict__ pred,
        const float* __restrict__ tgt,
        const int*   __restrict__ batch,
        const int*   __restrict__ mask,
        const float* __restrict__ sat_p,
        const float* __restrict__ sat_t,
        float*       __restrict__ out,
        int n4, int N, int B, float l1)
{
    const unsigned FULL = 0xffffffffu;
    const float4* pred4  = (const float4*)pred;
    const float4* tgt4   = (const float4*)tgt;
    const int4*   batch4 = (const int4*)batch;
    const int4*   mask4  = (const int4*)mask;

    // ---- node phase: proven round-5 shape, untouched ----
    int i = blockIdx.x * blockDim.x + threadIdx.x;
    if (i < n4) {
        float4 p4 = __ldcs(&pred4[i]);
        float4 t4 = __ldcs(&tgt4[i]);
        int4   s4 = __ldcs(&batch4[i]);
        int4   k4 = __ldcs(&mask4[i]);

        float m0 = (float)k4.x, m1 = (float)k4.y, m2 = (float)k4.z, m3 = (float)k4.w;
        float b0 = bce_fast(p4.x * m0, t4.x);
        float b1 = bce_fast(p4.y * m1, t4.y);
        float b2 = bce_fast(p4.z * m2, t4.z);
        float b3 = bce_fast(p4.w * m3, t4.w);

        unsigned act = __activemask();
        bool done = false;
        if (act == FULL) {
            int wlo = __shfl_sync(FULL, s4.x, 0);
            int whi = __shfl_sync(FULL, s4.w, 31);
            if (wlo == whi) {
                // 128 contiguous nodes in one segment (batch sorted)
                float b = (b0 + b1) + (b2 + b3);
                float m = (m0 + m1) + (m2 + m3);
                #pragma unroll
                for (int o = 16; o; o >>= 1) {
                    b += __shfl_down_sync(FULL, b, o);
                    m += __shfl_down_sync(FULL, m, o);
                }
                if ((threadIdx.x & 31) == 0) {
                    atomicAdd(&g_seg_bce[wlo], b);
                    atomicAdd(&g_seg_cnt[wlo], m);
                }
                done = true;
            }
        }
        if (!done) {
            if (s4.x == s4.w) {
                atomicAdd(&g_seg_bce[s4.x], (b0 + b1) + (b2 + b3));
                atomicAdd(&g_seg_cnt[s4.x], (m0 + m1) + (m2 + m3));
            } else {
                atomicAdd(&g_seg_bce[s4.x], b0); atomicAdd(&g_seg_cnt[s4.x], m0);
                atomicAdd(&g_seg_bce[s4.y], b1); atomicAdd(&g_seg_cnt[s4.y], m1);
                atomicAdd(&g_seg_bce[s4.z], b2); atomicAdd(&g_seg_cnt[s4.z], m2);
                atomicAdd(&g_seg_bce[s4.w], b3); atomicAdd(&g_seg_cnt[s4.w], m3);
            }
        }
    }

    // scalar tail (N % 4) — block 0
    int tail = N - (n4 << 2);
    if (tail > 0 && blockIdx.x == 0 && (int)threadIdx.x < tail) {
        int j = (n4 << 2) + threadIdx.x;
        float mm = (float)mask[j];
        atomicAdd(&g_seg_bce[batch[j]], bce_fast(pred[j] * mm, tgt[j]));
        atomicAdd(&g_seg_cnt[batch[j]], mm);
    }

    // ---- ticket: release-atomic only (NO per-block gpu fence / L1 flush) ----
    __shared__ int sh_last;
    __shared__ float sh[8];
    __syncthreads();                       // block's REDs all issued
    if (threadIdx.x == 0) {
        unsigned t = ticket_add_release(&g_ticket);
        sh_last = (t == (unsigned)gridDim.x - 1u) ? 1 : 0;
    }
    __syncthreads();
    if (!sh_last) return;

    // ---- last block only: acquire side + epilogue ----
    asm volatile("fence.acq_rel.gpu;" ::: "memory");   // single IVALL, one block

    float acc = 0.0f;
    for (int j = threadIdx.x; j < B; j += blockDim.x) {
        float c  = __ldcg(&g_seg_cnt[j]);
        float sb = __ldcg(&g_seg_bce[j]);
        acc += (c > 0.0f) ? (sb / fmaxf(c, 1.0f)) : 0.0f;
        acc += bce_fast(sat_p[j], sat_t[j]) * (l1 / (float)B);
        g_seg_cnt[j] = 0.0f;               // re-zero for next graph replay
        g_seg_bce[j] = 0.0f;
    }
    #pragma unroll
    for (int o = 16; o; o >>= 1) acc += __shfl_down_sync(FULL, acc, o);
    int lane = threadIdx.x & 31, wid = threadIdx.x >> 5;
    if (lane == 0) sh[wid] = acc;
    __syncthreads();
    if (wid == 0) {
        acc = (lane < (int)(blockDim.x >> 5)) ? sh[lane] : 0.0f;
        #pragma unroll
        for (int o = 16; o; o >>= 1) acc += __shfl_down_sync(FULL, acc, o);
        if (lane == 0) {
            out[0] = acc;
            atomicExch(&g_ticket, 0u);     // reset for next replay
        }
    }
}

extern "C" void kernel_launch(void* const* d_in, const int* in_sizes, int n_in,
                              void* d_out, int out_size) {
    const float* y_mus_pred = (const float*)d_in[0];
    const float* y_mus      = (const float*)d_in[1];
    const float* y_sat_pred = (const float*)d_in[2];
    const float* y_sat      = (const float*)d_in[3];
    const int*   batch      = (const int*)  d_in[4];
    const int*   mask       = (const int*)  d_in[5];
    int N = in_sizes[0];
    int B = in_sizes[2];
    float L1 = 1.0f / 50.0f;

    int n4 = N >> 2;
    int blocks = (n4 + 255) / 256;
    if (blocks < 1) blocks = 1;

    fused_kernel<<<blocks, 256>>>(y_mus_pred, y_mus, batch, mask,
                                  y_sat_pred, y_sat, (float*)d_out,
                                  n4, N, B, L1);
}

// round 9
// speedup vs baseline: 1.3056x; 1.3056x over previous
#include <cuda_runtime.h>
#include <math.h>

#define MAXB 4096
__device__ float    g_seg_bce[MAXB];   // zero-init at module load; last block re-zeroes
__device__ float    g_seg_cnt[MAXB];
__device__ unsigned g_ticket;          // zero-init; last block resets

__device__ __forceinline__ float bce_fast(float p, float t) {
    float lp = fmaxf(__logf(p),        -100.0f);   // __logf(0) = -inf -> -100
    float lq = fmaxf(__logf(1.0f - p), -100.0f);
    return -(t * lp + (1.0f - t) * lq);
}

__global__ void __launch_bounds__(256) fused_persistent_kernel(
        const float* __restrict__ pred,
        const float* __restrict__ tgt,
        const int*   __restrict__ batch,
        const int*   __restrict__ mask,
        const float* __restrict__ sat_p,
        const float* __restrict__ sat_t,
        float*       __restrict__ out,
        int n4, int N, int B, float l1)
{
    const unsigned FULL = 0xffffffffu;
    const float4* pred4  = (const float4*)pred;
    const float4* tgt4   = (const float4*)tgt;
    const int4*   batch4 = (const int4*)batch;
    const int4*   mask4  = (const int4*)mask;

    // ---- persistent node phase: grid-stride loop over float4 chunks ----
    int stride = gridDim.x * blockDim.x;
    for (int i = blockIdx.x * blockDim.x + threadIdx.x; i < n4; i += stride) {
        float4 p4 = __ldcs(&pred4[i]);
        float4 t4 = __ldcs(&tgt4[i]);
        int4   s4 = __ldcs(&batch4[i]);
        int4   k4 = __ldcs(&mask4[i]);

        float m0 = (float)k4.x, m1 = (float)k4.y, m2 = (float)k4.z, m3 = (float)k4.w;
        float b0 = bce_fast(p4.x * m0, t4.x);
        float b1 = bce_fast(p4.y * m1, t4.y);
        float b2 = bce_fast(p4.z * m2, t4.z);
        float b3 = bce_fast(p4.w * m3, t4.w);

        unsigned act = __activemask();
        bool done = false;
        if (act == FULL) {
            int wlo = __shfl_sync(FULL, s4.x, 0);
            int whi = __shfl_sync(FULL, s4.w, 31);
            if (wlo == whi) {
                // 128 contiguous nodes in one segment (batch sorted)
                float b = (b0 + b1) + (b2 + b3);
                float m = (m0 + m1) + (m2 + m3);
                #pragma unroll
                for (int o = 16; o; o >>= 1) {
                    b += __shfl_down_sync(FULL, b, o);
                    m += __shfl_down_sync(FULL, m, o);
                }
                if ((threadIdx.x & 31) == 0) {
                    atomicAdd(&g_seg_bce[wlo], b);
                    atomicAdd(&g_seg_cnt[wlo], m);
                }
                done = true;
            }
        }
        if (!done) {
            if (s4.x == s4.w) {
                atomicAdd(&g_seg_bce[s4.x], (b0 + b1) + (b2 + b3));
                atomicAdd(&g_seg_cnt[s4.x], (m0 + m1) + (m2 + m3));
            } else {
                atomicAdd(&g_seg_bce[s4.x], b0); atomicAdd(&g_seg_cnt[s4.x], m0);
                atomicAdd(&g_seg_bce[s4.y], b1); atomicAdd(&g_seg_cnt[s4.y], m1);
                atomicAdd(&g_seg_bce[s4.z], b2); atomicAdd(&g_seg_cnt[s4.z], m2);
                atomicAdd(&g_seg_bce[s4.w], b3); atomicAdd(&g_seg_cnt[s4.w], m3);
            }
        }
    }

    // scalar tail (N % 4) — block 0
    int tail = N - (n4 << 2);
    if (tail > 0 && blockIdx.x == 0 && (int)threadIdx.x < tail) {
        int j = (n4 << 2) + threadIdx.x;
        float mm = (float)mask[j];
        atomicAdd(&g_seg_bce[batch[j]], bce_fast(pred[j] * mm, tgt[j]));
        atomicAdd(&g_seg_cnt[batch[j]], mm);
    }

    // ---- ticket (only ~1184 CTAs; tail cost amortized over 8 resident/SM) ----
    __shared__ int sh_last;
    __shared__ float sh[8];
    __syncthreads();
    if (threadIdx.x == 0) {
        unsigned t;
        asm volatile("atom.add.release.gpu.global.u32 %0, [%1], 1;"
                     : "=r"(t) : "l"(&g_ticket) : "memory");
        sh_last = (t == (unsigned)gridDim.x - 1u) ? 1 : 0;
    }
    __syncthreads();
    if (!sh_last) return;

    // ---- last block only: acquire + epilogue ----
    asm volatile("fence.acq_rel.gpu;" ::: "memory");

    float acc = 0.0f;
    for (int j = threadIdx.x; j < B; j += blockDim.x) {
        float c  = __ldcg(&g_seg_cnt[j]);
        float sb = __ldcg(&g_seg_bce[j]);
        acc += (c > 0.0f) ? (sb / fmaxf(c, 1.0f)) : 0.0f;
        acc += bce_fast(sat_p[j], sat_t[j]) * (l1 / (float)B);
        g_seg_cnt[j] = 0.0f;               // re-zero for next graph replay
        g_seg_bce[j] = 0.0f;
    }
    #pragma unroll
    for (int o = 16; o; o >>= 1) acc += __shfl_down_sync(FULL, acc, o);
    int lane = threadIdx.x & 31, wid = threadIdx.x >> 5;
    if (lane == 0) sh[wid] = acc;
    __syncthreads();
    if (wid == 0) {
        acc = (lane < (int)(blockDim.x >> 5)) ? sh[lane] : 0.0f;
        #pragma unroll
        for (int o = 16; o; o >>= 1) acc += __shfl_down_sync(FULL, acc, o);
        if (lane == 0) {
            out[0] = acc;
            atomicExch(&g_ticket, 0u);     // reset for next replay
        }
    }
}

extern "C" void kernel_launch(void* const* d_in, const int* in_sizes, int n_in,
                              void* d_out, int out_size) {
    const float* y_mus_pred = (const float*)d_in[0];
    const float* y_mus      = (const float*)d_in[1];
    const float* y_sat_pred = (const float*)d_in[2];
    const float* y_sat      = (const float*)d_in[3];
    const int*   batch      = (const int*)  d_in[4];
    const int*   mask       = (const int*)  d_in[5];
    int N = in_sizes[0];
    int B = in_sizes[2];
    float L1 = 1.0f / 50.0f;

    int n4 = N >> 2;
    // persistent grid: 8 CTAs per SM on 148 SMs
    int blocks = 148 * 8;
    int max_blocks = (n4 + 255) / 256;
    if (max_blocks < 1) max_blocks = 1;
    if (blocks > max_blocks) blocks = max_blocks;

    fused_persistent_kernel<<<blocks, 256>>>(y_mus_pred, y_mus, batch, mask,
                                             y_sat_pred, y_sat, (float*)d_out,
                                             n4, N, B, L1);
}